// round 3
// baseline (speedup 1.0000x reference)
#include <cuda_runtime.h>
#include <cuda_bf16.h>
#include <cstdint>

// Problem constants (fixed by the reference setup_inputs)
#define N_USERS_C 200000
#define NN_C      300000          // N_USERS + N_ITEMS
#define D_C       64
#define NEDGES_C  1200000
#define NB1       293             // ceil(NN_C / 1024)
#define EB        4688            // ceil(NEDGES_C / 256)

// Scratch (device globals; zero-init at load).
// g_counts lifecycle per replay: hist fills -> scan1 reads+zeroes ->
// bucket uses as cursors (fills again) -> fused zeroes.
__device__ int  g_counts  [NN_C];
__device__ int  g_loc     [NN_C];      // block-local exclusive prefix
__device__ int  g_partials[NB1];       // per-1024-block totals -> exclusive
__device__ int2 g_edges   [NEDGES_C];  // (col, bitcast(val)) row-sorted
__device__ int  g_general;             // 1 if filt != eye(64)

// ---------------------------------------------------------------------------
// K0: per-row histogram; block 0 also checks filt == eye(64)
// ---------------------------------------------------------------------------
__global__ void __launch_bounds__(256)
k_hist_check(const int* __restrict__ adj_rows, const float* __restrict__ filt) {
    if (blockIdx.x == 0) {
        __shared__ int s_bad;
        if (threadIdx.x == 0) s_bad = 0;
        __syncthreads();
        int bad = 0;
        for (int i = threadIdx.x; i < D_C * D_C; i += 256) {
            float expect = ((i >> 6) == (i & 63)) ? 1.0f : 0.0f;
            if (filt[i] != expect) bad = 1;
        }
        if (bad) atomicOr(&s_bad, 1);
        __syncthreads();
        if (threadIdx.x == 0) g_general = s_bad;
    }
    int e = blockIdx.x * 256 + threadIdx.x;
    if (e < NEDGES_C) atomicAdd(&g_counts[adj_rows[e]], 1);
}

// ---------------------------------------------------------------------------
// K1: block-level exclusive scan of counts; emits block totals; zeroes counts
// ---------------------------------------------------------------------------
__global__ void __launch_bounds__(1024)
k_scan1() {
    __shared__ int s[1024];
    int idx = blockIdx.x * 1024 + threadIdx.x;
    int v = (idx < NN_C) ? g_counts[idx] : 0;
    if (idx < NN_C) g_counts[idx] = 0;   // reset for bucket-cursor use
    s[threadIdx.x] = v;
    __syncthreads();
    #pragma unroll
    for (int d = 1; d < 1024; d <<= 1) {
        int add = (threadIdx.x >= d) ? s[threadIdx.x - d] : 0;
        __syncthreads();
        s[threadIdx.x] += add;
        __syncthreads();
    }
    int incl = s[threadIdx.x];
    if (idx < NN_C) g_loc[idx] = incl - v;
    if (threadIdx.x == 1023) g_partials[blockIdx.x] = incl;
}

// K2: exclusive scan of the 293 block totals (single block)
__global__ void __launch_bounds__(512)
k_scan2() {
    __shared__ int s[512];
    int t = threadIdx.x;
    int v = (t < NB1) ? g_partials[t] : 0;
    s[t] = v;
    __syncthreads();
    #pragma unroll
    for (int d = 1; d < 512; d <<= 1) {
        int add = (t >= d) ? s[t - d] : 0;
        __syncthreads();
        s[t] += add;
        __syncthreads();
    }
    if (t < NB1) g_partials[t] = s[t] - v;
}

__device__ __forceinline__ int row_off(int r) {
    return (r < NN_C) ? (g_loc[r] + g_partials[r >> 10]) : NEDGES_C;
}

// ---------------------------------------------------------------------------
// K3: bucket edges into row-sorted CSR order (offset computed on the fly)
// ---------------------------------------------------------------------------
__global__ void __launch_bounds__(256)
k_bucket(const int* __restrict__ adj_rows,
         const int* __restrict__ adj_cols,
         const float* __restrict__ adj_vals) {
    int e = blockIdx.x * 256 + threadIdx.x;
    if (e >= NEDGES_C) return;
    int r = adj_rows[e];
    int pos = g_loc[r] + g_partials[r >> 10] + atomicAdd(&g_counts[r], 1);
    g_edges[pos] = make_int2(adj_cols[e], __float_as_int(adj_vals[e]));
}

// ---------------------------------------------------------------------------
// K4: fused segment-sum + finalize. One warp per row.
//     2 edges per iteration: lane = quarter (l&15) of edge i+(l>>4), float4.
//     Streaming stores for out so emb stays L2-resident for the gather.
// ---------------------------------------------------------------------------
__global__ void __launch_bounds__(256)
k_fused(const float* __restrict__ user_emb,
        const float* __restrict__ item_emb,
        const float* __restrict__ filt,
        float* __restrict__ out) {
    __shared__ float s_filt[D_C * D_C];   // general path only
    __shared__ float s_t[8][D_C];

    const int gen = g_general;            // uniform
    if (gen) {
        for (int i = threadIdx.x; i < D_C * D_C; i += blockDim.x)
            s_filt[i] = filt[i];
        __syncthreads();
    }

    const int w    = threadIdx.x >> 5;
    const int lane = threadIdx.x & 31;
    const int half = lane >> 4;           // 0 or 1: which edge of the pair
    const int q    = lane & 15;           // float4 quarter of the row
    const int r    = blockIdx.x * 8 + w;  // 37500*8 == 300000

    const int start = row_off(r);
    const int end   = row_off(r + 1);
    if (lane == 0) g_counts[r] = 0;       // reset cursors for next replay

    float4 acc = make_float4(0.f, 0.f, 0.f, 0.f);
    for (int i = start; i < end; i += 2) {
        int ei = i + half;
        if (ei < end) {
            int2 eg = g_edges[ei];        // broadcast within half-warp
            float val = __int_as_float(eg.y);
            const float4* src = (eg.x < N_USERS_C)
                ? (const float4*)(user_emb + (size_t)eg.x * D_C)
                : (const float4*)(item_emb + (size_t)(eg.x - N_USERS_C) * D_C);
            float4 vv = __ldg(&src[q]);
            acc.x = fmaf(val, vv.x, acc.x);
            acc.y = fmaf(val, vv.y, acc.y);
            acc.z = fmaf(val, vv.z, acc.z);
            acc.w = fmaf(val, vv.w, acc.w);
        }
    }
    // combine the two halves (lane l and l^16 hold the same quarter)
    acc.x += __shfl_xor_sync(0xffffffffu, acc.x, 16);
    acc.y += __shfl_xor_sync(0xffffffffu, acc.y, 16);
    acc.z += __shfl_xor_sync(0xffffffffu, acc.z, 16);
    acc.w += __shfl_xor_sync(0xffffffffu, acc.w, 16);

    const float4* esrc = (r < N_USERS_C)
        ? (const float4*)(user_emb + (size_t)r * D_C)
        : (const float4*)(item_emb + (size_t)(r - N_USERS_C) * D_C);
    float4 e = __ldg(&esrc[q]);           // broadcast across halves

    float4 t = make_float4(2.0f * e.x - acc.x, 2.0f * e.y - acc.y,
                           2.0f * e.z - acc.z, 2.0f * e.w - acc.w);

    float4* orow = (float4*)(out + (size_t)r * 128);

    if (!gen) {
        if (half == 0) {
            __stcs(&orow[q], e);          // [0:64) = emb
        } else {
            float4 h = make_float4(1.0f / (1.0f + __expf(-t.x)),
                                   1.0f / (1.0f + __expf(-t.y)),
                                   1.0f / (1.0f + __expf(-t.z)),
                                   1.0f / (1.0f + __expf(-t.w)));
            __stcs(&orow[16 + q], h);     // [64:128) = sigmoid(t)
        }
    } else {
        if (half == 0) {
            *(float4*)&s_t[w][4 * q] = t;
            __stcs(&orow[q], e);
        }
        __syncwarp();
        float a0 = 0.f, a1 = 0.f;
        const int c0 = 2 * lane, c1 = 2 * lane + 1;
        #pragma unroll 8
        for (int k = 0; k < D_C; k++) {
            float tk = s_t[w][k];
            a0 = fmaf(tk, s_filt[k * D_C + c0], a0);
            a1 = fmaf(tk, s_filt[k * D_C + c1], a1);
        }
        float2 h2 = make_float2(1.0f / (1.0f + __expf(-a0)),
                                1.0f / (1.0f + __expf(-a1)));
        __stcs((float2*)(out + (size_t)r * 128 + 64) + lane, h2);
    }
}

// ---------------------------------------------------------------------------
// Launch. Inputs (metadata order):
//   0: adj_rows (i32 1.2M)  1: adj_cols (i32 1.2M)  2: adj_vals (f32 1.2M)
//   3: user_emb (f32 200000*64)  4: item_emb (f32 100000*64)  5: filt (64*64)
// Output: 300000 rows of [emb | h] (f32, 128 wide), users then items.
// ---------------------------------------------------------------------------
extern "C" void kernel_launch(void* const* d_in, const int* in_sizes, int n_in,
                              void* d_out, int out_size) {
    const int*   adj_rows = (const int*)  d_in[0];
    const int*   adj_cols = (const int*)  d_in[1];
    const float* adj_vals = (const float*)d_in[2];
    const float* user_emb = (const float*)d_in[3];
    const float* item_emb = (const float*)d_in[4];
    const float* filt     = (const float*)d_in[5];
    float* out = (float*)d_out;

    k_hist_check<<<EB, 256>>>(adj_rows, filt);
    k_scan1     <<<NB1, 1024>>>();
    k_scan2     <<<1, 512>>>();
    k_bucket    <<<EB, 256>>>(adj_rows, adj_cols, adj_vals);
    k_fused     <<<NN_C / 8, 256>>>(user_emb, item_emb, filt, out);
}